// round 15
// baseline (speedup 1.0000x reference)
#include <cuda_runtime.h>
#include <cuda_fp16.h>
#include <cstdint>
#include <cstddef>

// ---------------- Problem constants ----------------
#define NNODES 200000
#define NEDGES 400000
#define NGRAPHS 4096
#define HDIM 300
#define H2DIM 600
#define NLAYERS 5
#define KP1 320   // padded K for gemm1 operands (>=300, mult of 32)
#define KP2 608   // padded K for gemm2 operands (>=600, mult of 32)

// ---------------- Scratch (device globals; no allocation allowed) ----------------
__device__ float g_h[(size_t)NNODES * HDIM];      // node features (fp32)
__device__ float g_agg[(size_t)NNODES * HDIM];    // scatter-add accumulator
__device__ __half g_a0[(size_t)NNODES * KP1];     // gemm1 A hi-split
__device__ __half g_a1[(size_t)NNODES * KP1];     // gemm1 A lo-split
__device__ __half g_t0[(size_t)NNODES * KP2];     // gemm1 out / gemm2 A hi-split
__device__ __half g_t1[(size_t)NNODES * KP2];     // lo-split
__device__ __half g_w1p0[(size_t)NLAYERS * H2DIM * KP1];  // W1 transposed+split [l][n][k]
__device__ __half g_w1p1[(size_t)NLAYERS * H2DIM * KP1];
__device__ __half g_w2p0[(size_t)NLAYERS * HDIM * KP2];   // W2 transposed+split
__device__ __half g_w2p1[(size_t)NLAYERS * HDIM * KP2];
__device__ float g_gsum[(size_t)NGRAPHS * HDIM];
__device__ float g_gcnt[NGRAPHS];

// ---------------- PTX helpers ----------------
__device__ __forceinline__ void red_add_v4(float* p, float4 v) {
    asm volatile("red.global.add.v4.f32 [%0], {%1, %2, %3, %4};"
                 :: "l"(p), "f"(v.x), "f"(v.y), "f"(v.z), "f"(v.w) : "memory");
}
__device__ __forceinline__ uint32_t smem_u32(const void* p) {
    uint32_t a;
    asm("{ .reg .u64 t; cvta.to.shared.u64 t, %1; cvt.u32.u64 %0, t; }" : "=r"(a) : "l"(p));
    return a;
}
__device__ __forceinline__ void mma_f16(float* d, const unsigned* a, const unsigned* b) {
    asm volatile(
        "mma.sync.aligned.m16n8k16.row.col.f32.f16.f16.f32 "
        "{%0,%1,%2,%3}, {%4,%5,%6,%7}, {%8,%9}, {%0,%1,%2,%3};"
        : "+f"(d[0]), "+f"(d[1]), "+f"(d[2]), "+f"(d[3])
        : "r"(a[0]), "r"(a[1]), "r"(a[2]), "r"(a[3]), "r"(b[0]), "r"(b[1]));
}
__device__ __forceinline__ void ldm_x4(unsigned* r, uint32_t addr) {
    asm volatile("ldmatrix.sync.aligned.m8n8.x4.shared.b16 {%0,%1,%2,%3}, [%4];"
                 : "=r"(r[0]), "=r"(r[1]), "=r"(r[2]), "=r"(r[3]) : "r"(addr));
}
__device__ __forceinline__ void split2(float v, __half& h0, __half& h1) {
    h0 = __float2half_rn(v);
    h1 = __float2half_rn(v - __half2float(h0));
}
// cp.async 16B with zero-fill when !pred (src-size=0)
__device__ __forceinline__ void cp_async16(uint32_t dst, const void* src, bool pred) {
    int sz = pred ? 16 : 0;
    asm volatile("cp.async.ca.shared.global [%0], [%1], 16, %2;"
                 :: "r"(dst), "l"(src), "r"(sz) : "memory");
}
__device__ __forceinline__ void cp_commit() {
    asm volatile("cp.async.commit_group;" ::: "memory");
}
template <int N>
__device__ __forceinline__ void cp_wait() {
    asm volatile("cp.async.wait_group %0;" :: "n"(N) : "memory");
}

// ---------------- Zeroing kernels ----------------
__global__ void zero_agg_kernel() {
    float4* p = reinterpret_cast<float4*>(g_agg);
    int n4 = (NNODES * HDIM) / 4;
    for (int i = blockIdx.x * blockDim.x + threadIdx.x; i < n4; i += gridDim.x * blockDim.x)
        p[i] = make_float4(0.f, 0.f, 0.f, 0.f);
}
__global__ void zero_pool_kernel() {
    float4* p = reinterpret_cast<float4*>(g_gsum);
    int n4 = (NGRAPHS * HDIM) / 4;
    for (int i = blockIdx.x * blockDim.x + threadIdx.x; i < n4; i += gridDim.x * blockDim.x)
        p[i] = make_float4(0.f, 0.f, 0.f, 0.f);
    for (int i = blockIdx.x * blockDim.x + threadIdx.x; i < NGRAPHS; i += gridDim.x * blockDim.x)
        g_gcnt[i] = 0.f;
}

// ---------------- Weight prepack: transpose + fp16 split, all layers ----------------
#define W1P_TOTAL (NLAYERS * H2DIM * KP1)
#define W2P_TOTAL (NLAYERS * HDIM * KP2)
__global__ void prepack_w_kernel(const float* __restrict__ W1, const float* __restrict__ W2) {
    int idx = blockIdx.x * blockDim.x + threadIdx.x;
    if (idx < W1P_TOTAL) {
        int l = idx / (H2DIM * KP1);
        int rem = idx % (H2DIM * KP1);
        int n = rem / KP1, k = rem % KP1;
        float v = (k < HDIM) ? __ldg(&W1[((size_t)l * HDIM + k) * H2DIM + n]) : 0.f;
        __half h0, h1;
        split2(v, h0, h1);
        g_w1p0[idx] = h0;
        g_w1p1[idx] = h1;
    } else if (idx < W1P_TOTAL + W2P_TOTAL) {
        int j = idx - W1P_TOTAL;
        int l = j / (HDIM * KP2);
        int rem = j % (HDIM * KP2);
        int n = rem / KP2, k = rem % KP2;
        float v = (k < H2DIM) ? __ldg(&W2[((size_t)l * H2DIM + k) * HDIM + n]) : 0.f;
        __half h0, h1;
        split2(v, h0, h1);
        g_w2p0[j] = h0;
        g_w2p1[j] = h1;
    }
}

// ---------------- A prepack for gemm1: v=(1+eps)h+agg, split -> g_a0/g_a1 ----------------
// Also re-zeros g_agg in place so the next layer's edge scatter starts clean
// (replaces the separate zero_agg launch for layers 1..L-1).
__global__ void prepack_a_kernel(const float* __restrict__ epsp) {
    int idx = blockIdx.x * blockDim.x + threadIdx.x;  // row * 80 + g4
    if (idx >= NNODES * 80) return;
    int row = idx / 80, g4 = idx % 80;
    __half2 z0[2], z1[2];
    if (g4 < 75) {
        float epv = 1.0f + __ldg(epsp);
        float4 hv = *reinterpret_cast<const float4*>(g_h + (size_t)row * HDIM + g4 * 4);
        float4 gv = *reinterpret_cast<const float4*>(g_agg + (size_t)row * HDIM + g4 * 4);
        float v[4] = {fmaf(epv, hv.x, gv.x), fmaf(epv, hv.y, gv.y),
                      fmaf(epv, hv.z, gv.z), fmaf(epv, hv.w, gv.w)};
        __half h0[4], h1[4];
#pragma unroll
        for (int j = 0; j < 4; j++) split2(v[j], h0[j], h1[j]);
        z0[0] = __halves2half2(h0[0], h0[1]);
        z0[1] = __halves2half2(h0[2], h0[3]);
        z1[0] = __halves2half2(h1[0], h1[1]);
        z1[1] = __halves2half2(h1[2], h1[3]);
        // re-zero agg for next layer
        *reinterpret_cast<float4*>(g_agg + (size_t)row * HDIM + g4 * 4) =
            make_float4(0.f, 0.f, 0.f, 0.f);
    } else {
        z0[0] = z0[1] = z1[0] = z1[1] = __halves2half2(__ushort_as_half(0), __ushort_as_half(0));
    }
    *reinterpret_cast<__half2*>(g_a0 + (size_t)row * KP1 + g4 * 4) = z0[0];
    *reinterpret_cast<__half2*>(g_a0 + (size_t)row * KP1 + g4 * 4 + 2) = z0[1];
    *reinterpret_cast<__half2*>(g_a1 + (size_t)row * KP1 + g4 * 4) = z1[0];
    *reinterpret_cast<__half2*>(g_a1 + (size_t)row * KP1 + g4 * 4 + 2) = z1[1];
}

// ---------------- Atom encoder ----------------
__global__ void atom_kernel(const int* __restrict__ x, const float* __restrict__ atom_emb) {
    int n = blockIdx.x;
    __shared__ int sx[9];
    if (threadIdx.x < 9) sx[threadIdx.x] = x[n * 9 + threadIdx.x];
    __syncthreads();
    for (int j = threadIdx.x; j < HDIM; j += blockDim.x) {
        float s = 0.f;
#pragma unroll
        for (int f = 0; f < 9; f++)
            s += __ldg(&atom_emb[((size_t)(f * 120 + sx[f])) * HDIM + j]);
        g_h[(size_t)n * HDIM + j] = s;
    }
}

// ---------------- Edge kernel: agg[dst] += relu(h[src] + e) ----------------
__global__ void edge_kernel(const int* __restrict__ edge_index,
                            const int* __restrict__ edge_attr,
                            const float* __restrict__ bond_l) {
    int e = blockIdx.x * 8 + (threadIdx.x >> 5);
    if (e >= NEDGES) return;
    int lane = threadIdx.x & 31;
    int src = __ldg(&edge_index[e]);
    int dst = __ldg(&edge_index[NEDGES + e]);
    int a0 = __ldg(&edge_attr[e * 3 + 0]);
    int a1 = __ldg(&edge_attr[e * 3 + 1]);
    int a2 = __ldg(&edge_attr[e * 3 + 2]);
    const float4* b0 = reinterpret_cast<const float4*>(bond_l + (size_t)(0 * 16 + a0) * HDIM);
    const float4* b1 = reinterpret_cast<const float4*>(bond_l + (size_t)(1 * 16 + a1) * HDIM);
    const float4* b2 = reinterpret_cast<const float4*>(bond_l + (size_t)(2 * 16 + a2) * HDIM);
    const float4* hs = reinterpret_cast<const float4*>(g_h + (size_t)src * HDIM);
    float* ag = g_agg + (size_t)dst * HDIM;
#pragma unroll 3
    for (int c = lane; c < HDIM / 4; c += 32) {
        float4 e0 = __ldg(&b0[c]);
        float4 e1 = __ldg(&b1[c]);
        float4 e2 = __ldg(&b2[c]);
        float4 hv = hs[c];
        float4 m;
        m.x = fmaxf(hv.x + e0.x + e1.x + e2.x, 0.f);
        m.y = fmaxf(hv.y + e0.y + e1.y + e2.y, 0.f);
        m.z = fmaxf(hv.z + e0.z + e1.z + e2.z, 0.f);
        m.w = fmaxf(hv.w + e0.w + e1.w + e2.w, 0.f);
        red_add_v4(ag + 4 * c, m);
    }
}

// ---------------- Tensor-core GEMM (prepacked 3xFP16 split, cp.async pipeline) ----------------
// 512 threads (16 warps, 4x4), block tile 128x128, warp tile 32x32, K-chunk 32.
// 3-stage cp.async ring; stages of 4 tiles (Ah, Al, Bh, Bl), each 128x32 half (8KB),
// XOR-swizzled 16B chunks (conflict-free STS + ldmatrix).
// acc += Ah*Bh + Ah*Bl + Al*Bh.
// Padding-skip: n-slices with base >= NC and (MODE 1) the all-pad final kc are
// skipped with warp-uniform guards — MMA-pipe work drops, correctness unchanged
// (pad B columns are zero; g_t pad band is written explicitly in the epilogue).
#define TILE_B 8192
#define STAGE_B (4 * TILE_B)
#define NSTAGE 3
#define GSMEM (NSTAGE * STAGE_B)

template <int MODE>
__global__ __launch_bounds__(512) void gemm_f16_kernel(
    int l,
    const float* __restrict__ bias,
    const float* __restrict__ gml, const float* __restrict__ btl,
    const float* __restrict__ mnl, const float* __restrict__ vrl) {
    constexpr int KP = (MODE == 1) ? KP1 : KP2;
    constexpr int NC = (MODE == 1) ? H2DIM : HDIM;
    constexpr int NKT = KP / 32;

    extern __shared__ __align__(128) char smem[];
    const uint32_t sb = smem_u32(smem);

    const __half* Ah = (MODE == 1) ? g_a0 : g_t0;
    const __half* Al = (MODE == 1) ? g_a1 : g_t1;
    const __half* Bh = (MODE == 1) ? (g_w1p0 + (size_t)l * H2DIM * KP1)
                                   : (g_w2p0 + (size_t)l * HDIM * KP2);
    const __half* Bl = (MODE == 1) ? (g_w1p1 + (size_t)l * H2DIM * KP1)
                                   : (g_w2p1 + (size_t)l * HDIM * KP2);

    int tid = threadIdx.x;
    int lane = tid & 31, w = tid >> 5;
    int wr = w & 3, wc = w >> 2;
    int gid = lane >> 2, tig = lane & 3;
    int ml = lane & 15, khalf = lane >> 4;
    int rowBase = blockIdx.y * 128, colBase = blockIdx.x * 128;

    // Warp-uniform n-slice validity (16-col granularity)
    bool ngok[2];
#pragma unroll
    for (int ng = 0; ng < 2; ng++)
        ngok[ng] = (colBase + wc * 32 + ng * 16) < NC;
    bool anyng = ngok[0] || ngok[1];

    // cp.async mapping: thread -> (lrow, w4); each kt advances 64 bytes along K
    int lrow = tid >> 2, w4 = tid & 3;
    int garow = rowBase + lrow;
    int gbrow = colBase + lrow;
    bool aok = (garow < NNODES);
    bool bok = (gbrow < NC);
    int sa_row = aok ? garow : 0;  // safe address base even when predicated off
    int sb_row = bok ? gbrow : 0;
    const char* pAh = reinterpret_cast<const char*>(Ah + (size_t)sa_row * KP + w4 * 8);
    const char* pAl = reinterpret_cast<const char*>(Al + (size_t)sa_row * KP + w4 * 8);
    const char* pBh = reinterpret_cast<const char*>(Bh + (size_t)sb_row * KP + w4 * 8);
    const char* pBl = reinterpret_cast<const char*>(Bl + (size_t)sb_row * KP + w4 * 8);
    uint32_t sts_off = (uint32_t)lrow * 64 + (uint32_t)((w4 ^ ((lrow >> 1) & 3)) * 16);

    float acc[2][4][4];
#pragma unroll
    for (int mt = 0; mt < 2; mt++)
#pragma unroll
        for (int nt = 0; nt < 4; nt++)
#pragma unroll
            for (int i = 0; i < 4; i++) acc[mt][nt][i] = 0.f;

    auto issue_stage = [&](int kt) {
        uint32_t st = sb + (uint32_t)(kt % NSTAGE) * STAGE_B + sts_off;
        size_t go = (size_t)kt * 64;
        cp_async16(st + 0 * TILE_B, pAh + go, aok);
        cp_async16(st + 1 * TILE_B, pAl + go, aok);
        cp_async16(st + 2 * TILE_B, pBh + go, bok);
        cp_async16(st + 3 * TILE_B, pBl + go, bok);
    };

    issue_stage(0);
    cp_commit();
    issue_stage(1);
    cp_commit();

    for (int kt = 0; kt < NKT; kt++) {
        if (kt + 2 < NKT) issue_stage(kt + 2);
        cp_commit();
        cp_wait<2>();
        __syncthreads();

        uint32_t stg = sb + (uint32_t)(kt % NSTAGE) * STAGE_B;
        // MODE 1 final chunk: kc=1 covers k 304..319, entirely zero padding -> skip
        int kcmax = (MODE == 1 && kt == NKT - 1) ? 1 : 2;
        for (int kc = 0; kc < kcmax; kc++) {
            unsigned ahf[2][4], alf[2][4], bhf[2][4], blf[2][4];
            if (anyng) {
#pragma unroll
                for (int mt = 0; mt < 2; mt++) {
                    int r = wr * 32 + mt * 16 + ml;
                    uint32_t off = (uint32_t)r * 64 +
                                   (uint32_t)(((kc * 2 + khalf) ^ ((r >> 1) & 3)) * 16);
                    ldm_x4(ahf[mt], stg + 0 * TILE_B + off);
                    ldm_x4(alf[mt], stg + 1 * TILE_B + off);
                }
#pragma unroll
                for (int ng = 0; ng < 2; ng++) {
                    if (!ngok[ng]) continue;
                    int r = wc * 32 + ng * 16 + ml;
                    uint32_t off = (uint32_t)r * 64 +
                                   (uint32_t)(((kc * 2 + khalf) ^ ((r >> 1) & 3)) * 16);
                    ldm_x4(bhf[ng], stg + 2 * TILE_B + off);
                    ldm_x4(blf[ng], stg + 3 * TILE_B + off);
                }
#pragma unroll
                for (int mt = 0; mt < 2; mt++)
#pragma unroll
                    for (int ng = 0; ng < 2; ng++) {
                        if (!ngok[ng]) continue;
#pragma unroll
                        for (int sn = 0; sn < 2; sn++) {
                            unsigned bh2[2] = {bhf[ng][sn], bhf[ng][sn + 2]};
                            unsigned bl2[2] = {blf[ng][sn], blf[ng][sn + 2]};
                            float* a = acc[mt][ng * 2 + sn];
                            mma_f16(a, ahf[mt], bh2);
                            mma_f16(a, ahf[mt], bl2);
                            mma_f16(a, alf[mt], bh2);
                        }
                    }
            }
        }
        __syncthreads();
    }

    // ---- Epilogue ----
#pragma unroll
    for (int mt = 0; mt < 2; mt++)
#pragma unroll
        for (int ng = 0; ng < 2; ng++)
#pragma unroll
            for (int sn = 0; sn < 2; sn++) {
                int c = colBase + wc * 32 + ng * 16 + sn * 8 + 2 * tig;
                int r0 = rowBase + wr * 32 + mt * 16 + gid;
                int r1 = r0 + 8;
                float* a = acc[mt][ng * 2 + sn];
                if (MODE == 1) {
                    if (c < H2DIM) {
                        float s0 = __ldg(&gml[c]) * rsqrtf(__ldg(&vrl[c]) + 1e-5f);
                        float t0 = (__ldg(&bias[c]) - __ldg(&mnl[c])) * s0 + __ldg(&btl[c]);
                        float s1 = __ldg(&gml[c + 1]) * rsqrtf(__ldg(&vrl[c + 1]) + 1e-5f);
                        float t1 = (__ldg(&bias[c + 1]) - __ldg(&mnl[c + 1])) * s1 + __ldg(&btl[c + 1]);
                        if (r0 < NNODES) {
                            float v0 = fmaxf(fmaf(a[0], s0, t0), 0.f);
                            float v1 = fmaxf(fmaf(a[1], s1, t1), 0.f);
                            __half h00, h01, h10, h11;
                            split2(v0, h00, h10);
                            split2(v1, h01, h11);
                            *reinterpret_cast<__half2*>(g_t0 + (size_t)r0 * KP2 + c) =
                                __halves2half2(h00, h01);
                            *reinterpret_cast<__half2*>(g_t1 + (size_t)r0 * KP2 + c) =
                                __halves2half2(h10, h11);
                        }
                        if (r1 < NNODES) {
                            float v0 = fmaxf(fmaf(a[2], s0, t0), 0.f);
                            float v1 = fmaxf(fmaf(a[3], s1, t1), 0.f);
                            __half h00, h01, h10, h11;
                            split2(v0, h00, h10);
                            split2(v1, h01, h11);
                            *reinterpret_cast<__half2*>(g_t0 + (size_t)r1 * KP2 + c) =
                                __halves2half2(h00, h01);
                            *reinterpret_cast<__half2*>(g_t1 + (size_t)r1 * KP2 + c) =
                                __halves2half2(h10, h11);
                        }
                    } else if (c < KP2) {
                        __half2 z = __halves2half2(__ushort_as_half(0), __ushort_as_half(0));
                        if (r0 < NNODES) {
                            *reinterpret_cast<__half2*>(g_t0 + (size_t)r0 * KP2 + c) = z;
                            *reinterpret_cast<__half2*>(g_t1 + (size_t)r0 * KP2 + c) = z;
                        }
                        if (r1 < NNODES) {
                            *reinterpret_cast<__half2*>(g_t0 + (size_t)r1 * KP2 + c) = z;
                            *reinterpret_cast<__half2*>(g_t1 + (size_t)r1 * KP2 + c) = z;
                        }
                    }
                } else {
                    if (c < HDIM) {
                        float t0 = __ldg(&bias[c]);
                        float t1 = __ldg(&bias[c + 1]);
                        if (r0 < NNODES) {
                            float2 o = make_float2(a[0] + t0, a[1] + t1);
                            *reinterpret_cast<float2*>(g_h + (size_t)r0 * HDIM + c) = o;
                        }
                        if (r1 < NNODES) {
                            float2 o = make_float2(a[2] + t0, a[3] + t1);
                            *reinterpret_cast<float2*>(g_h + (size_t)r1 * HDIM + c) = o;
                        }
                    }
                }
            }
}

// ---------------- Pooling scatter ----------------
__global__ void pool_kernel(const int* __restrict__ batch) {
    int n = blockIdx.x * 8 + (threadIdx.x >> 5);
    if (n >= NNODES) return;
    int lane = threadIdx.x & 31;
    int g = __ldg(&batch[n]);
    const float4* hr = reinterpret_cast<const float4*>(g_h + (size_t)n * HDIM);
    float* gs = g_gsum + (size_t)g * HDIM;
#pragma unroll 3
    for (int c = lane; c < HDIM / 4; c += 32)
        red_add_v4(gs + 4 * c, hr[c]);
    if (lane == 0) atomicAdd(&g_gcnt[g], 1.0f);
}

// ---------------- Final: graph_feature + logits ----------------
__global__ void final_kernel(const float* __restrict__ cls_W, const float* __restrict__ cls_b,
                             float* __restrict__ out, int write_gf) {
    int g = blockIdx.x;
    int tid = threadIdx.x;
    float inv = 1.0f / fmaxf(g_gcnt[g], 1.0f);
    float d0 = 0.f, d1 = 0.f;
    for (int j = tid; j < HDIM; j += blockDim.x) {
        float gf = g_gsum[(size_t)g * HDIM + j] * inv;
        if (write_gf) out[2 * NGRAPHS + (size_t)g * HDIM + j] = gf;
        d0 += gf * __ldg(&cls_W[j * 2 + 0]);
        d1 += gf * __ldg(&cls_W[j * 2 + 1]);
    }
    __shared__ float s0[128], s1[128];
    s0[tid] = d0;
    s1[tid] = d1;
    __syncthreads();
    for (int o = 64; o > 0; o >>= 1) {
        if (tid < o) { s0[tid] += s0[tid + o]; s1[tid] += s1[tid + o]; }
        __syncthreads();
    }
    if (tid == 0) {
        out[g * 2 + 0] = s0[0] + __ldg(&cls_b[0]);
        out[g * 2 + 1] = s1[0] + __ldg(&cls_b[1]);
    }
}

// ---------------- Launcher ----------------
extern "C" void kernel_launch(void* const* d_in, const int* in_sizes, int n_in,
                              void* d_out, int out_size) {
    const int* x          = (const int*)d_in[0];
    const int* edge_index = (const int*)d_in[1];
    const int* edge_attr  = (const int*)d_in[2];
    const int* batch      = (const int*)d_in[3];
    const float* atom_emb = (const float*)d_in[4];
    const float* bond_emb = (const float*)d_in[5];
    const float* eps      = (const float*)d_in[6];
    const float* W1       = (const float*)d_in[7];
    const float* b1       = (const float*)d_in[8];
    const float* bn_gamma = (const float*)d_in[9];
    const float* bn_beta  = (const float*)d_in[10];
    const float* bn_mean  = (const float*)d_in[11];
    const float* bn_var   = (const float*)d_in[12];
    const float* W2       = (const float*)d_in[13];
    const float* b2       = (const float*)d_in[14];
    const float* cls_W    = (const float*)d_in[15];
    const float* cls_b    = (const float*)d_in[16];
    float* out = (float*)d_out;

    cudaFuncSetAttribute(gemm_f16_kernel<1>, cudaFuncAttributeMaxDynamicSharedMemorySize, GSMEM);
    cudaFuncSetAttribute(gemm_f16_kernel<2>, cudaFuncAttributeMaxDynamicSharedMemorySize, GSMEM);

    atom_kernel<<<NNODES, 128>>>(x, atom_emb);
    zero_pool_kernel<<<1184, 256>>>();
    prepack_w_kernel<<<(W1P_TOTAL + W2P_TOTAL + 255) / 256, 256>>>(W1, W2);
    zero_agg_kernel<<<4096, 256>>>();  // layer 0 only; prepack_a re-zeros thereafter

    dim3 g1grid(5, (NNODES + 127) / 128);
    dim3 g2grid(3, (NNODES + 127) / 128);

    for (int l = 0; l < NLAYERS; l++) {
        edge_kernel<<<(NEDGES + 7) / 8, 256>>>(edge_index, edge_attr,
                                               bond_emb + (size_t)l * 3 * 16 * HDIM);
        prepack_a_kernel<<<(NNODES * 80 + 255) / 256, 256>>>(eps + l);
        gemm_f16_kernel<1><<<g1grid, 512, GSMEM>>>(
            l, b1 + (size_t)l * H2DIM,
            bn_gamma + (size_t)l * H2DIM, bn_beta + (size_t)l * H2DIM,
            bn_mean + (size_t)l * H2DIM, bn_var + (size_t)l * H2DIM);
        gemm_f16_kernel<2><<<g2grid, 512, GSMEM>>>(
            l, b2 + (size_t)l * HDIM, nullptr, nullptr, nullptr, nullptr);
    }

    pool_kernel<<<(NNODES + 7) / 8, 256>>>(batch);
    int write_gf = (out_size >= 2 * NGRAPHS + NGRAPHS * HDIM) ? 1 : 0;
    final_kernel<<<NGRAPHS, 128>>>(cls_W, cls_b, out, write_gf);
}

// round 16
// speedup vs baseline: 1.4660x; 1.4660x over previous
#include <cuda_runtime.h>
#include <cuda_fp16.h>
#include <cstdint>
#include <cstddef>

// ---------------- Problem constants ----------------
#define NNODES 200000
#define NEDGES 400000
#define NGRAPHS 4096
#define HDIM 300
#define H2DIM 600
#define NLAYERS 5
#define KP1 320   // padded K for gemm1 operands (>=300, mult of 32)
#define KP2 608   // padded K for gemm2 operands (>=600, mult of 32)

// ---------------- Scratch (device globals; no allocation allowed) ----------------
__device__ float g_h[(size_t)NNODES * HDIM];      // node features (fp32)
__device__ float g_agg[(size_t)NNODES * HDIM];    // scatter-add accumulator
__device__ __half g_a0[(size_t)NNODES * KP1];     // gemm1 A hi-split
__device__ __half g_a1[(size_t)NNODES * KP1];     // gemm1 A lo-split
__device__ __half g_t0[(size_t)NNODES * KP2];     // gemm1 out / gemm2 A hi-split
__device__ __half g_t1[(size_t)NNODES * KP2];     // lo-split
__device__ __half g_w1p0[(size_t)NLAYERS * H2DIM * KP1];  // W1 transposed+split [l][n][k]
__device__ __half g_w1p1[(size_t)NLAYERS * H2DIM * KP1];
__device__ __half g_w2p0[(size_t)NLAYERS * HDIM * KP2];   // W2 transposed+split
__device__ __half g_w2p1[(size_t)NLAYERS * HDIM * KP2];
__device__ float g_gsum[(size_t)NGRAPHS * HDIM];
__device__ float g_gcnt[NGRAPHS];

// ---------------- PTX helpers ----------------
__device__ __forceinline__ void red_add_v4(float* p, float4 v) {
    asm volatile("red.global.add.v4.f32 [%0], {%1, %2, %3, %4};"
                 :: "l"(p), "f"(v.x), "f"(v.y), "f"(v.z), "f"(v.w) : "memory");
}
__device__ __forceinline__ uint32_t smem_u32(const void* p) {
    uint32_t a;
    asm("{ .reg .u64 t; cvta.to.shared.u64 t, %1; cvt.u32.u64 %0, t; }" : "=r"(a) : "l"(p));
    return a;
}
__device__ __forceinline__ void mma_f16(float* d, const unsigned* a, const unsigned* b) {
    asm volatile(
        "mma.sync.aligned.m16n8k16.row.col.f32.f16.f16.f32 "
        "{%0,%1,%2,%3}, {%4,%5,%6,%7}, {%8,%9}, {%0,%1,%2,%3};"
        : "+f"(d[0]), "+f"(d[1]), "+f"(d[2]), "+f"(d[3])
        : "r"(a[0]), "r"(a[1]), "r"(a[2]), "r"(a[3]), "r"(b[0]), "r"(b[1]));
}
__device__ __forceinline__ void ldm_x4(unsigned* r, uint32_t addr) {
    asm volatile("ldmatrix.sync.aligned.m8n8.x4.shared.b16 {%0,%1,%2,%3}, [%4];"
                 : "=r"(r[0]), "=r"(r[1]), "=r"(r[2]), "=r"(r[3]) : "r"(addr));
}
__device__ __forceinline__ void split2(float v, __half& h0, __half& h1) {
    h0 = __float2half_rn(v);
    h1 = __float2half_rn(v - __half2float(h0));
}
// cp.async 16B with zero-fill when !pred (src-size=0)
__device__ __forceinline__ void cp_async16(uint32_t dst, const void* src, bool pred) {
    int sz = pred ? 16 : 0;
    asm volatile("cp.async.ca.shared.global [%0], [%1], 16, %2;"
                 :: "r"(dst), "l"(src), "r"(sz) : "memory");
}
__device__ __forceinline__ void cp_commit() {
    asm volatile("cp.async.commit_group;" ::: "memory");
}
template <int N>
__device__ __forceinline__ void cp_wait() {
    asm volatile("cp.async.wait_group %0;" :: "n"(N) : "memory");
}

// ---------------- Zeroing kernels ----------------
__global__ void zero_agg_kernel() {
    float4* p = reinterpret_cast<float4*>(g_agg);
    int n4 = (NNODES * HDIM) / 4;
    for (int i = blockIdx.x * blockDim.x + threadIdx.x; i < n4; i += gridDim.x * blockDim.x)
        p[i] = make_float4(0.f, 0.f, 0.f, 0.f);
}
__global__ void zero_pool_kernel() {
    float4* p = reinterpret_cast<float4*>(g_gsum);
    int n4 = (NGRAPHS * HDIM) / 4;
    for (int i = blockIdx.x * blockDim.x + threadIdx.x; i < n4; i += gridDim.x * blockDim.x)
        p[i] = make_float4(0.f, 0.f, 0.f, 0.f);
    for (int i = blockIdx.x * blockDim.x + threadIdx.x; i < NGRAPHS; i += gridDim.x * blockDim.x)
        g_gcnt[i] = 0.f;
}

// ---------------- Weight prepack: transpose + fp16 split, all layers ----------------
#define W1P_TOTAL (NLAYERS * H2DIM * KP1)
#define W2P_TOTAL (NLAYERS * HDIM * KP2)
__global__ void prepack_w_kernel(const float* __restrict__ W1, const float* __restrict__ W2) {
    int idx = blockIdx.x * blockDim.x + threadIdx.x;
    if (idx < W1P_TOTAL) {
        int l = idx / (H2DIM * KP1);
        int rem = idx % (H2DIM * KP1);
        int n = rem / KP1, k = rem % KP1;
        float v = (k < HDIM) ? __ldg(&W1[((size_t)l * HDIM + k) * H2DIM + n]) : 0.f;
        __half h0, h1;
        split2(v, h0, h1);
        g_w1p0[idx] = h0;
        g_w1p1[idx] = h1;
    } else if (idx < W1P_TOTAL + W2P_TOTAL) {
        int j = idx - W1P_TOTAL;
        int l = j / (HDIM * KP2);
        int rem = j % (HDIM * KP2);
        int n = rem / KP2, k = rem % KP2;
        float v = (k < H2DIM) ? __ldg(&W2[((size_t)l * H2DIM + k) * HDIM + n]) : 0.f;
        __half h0, h1;
        split2(v, h0, h1);
        g_w2p0[j] = h0;
        g_w2p1[j] = h1;
    }
}

// ---------------- A prepack for gemm1: v=(1+eps)h+agg, split -> g_a0/g_a1 ----------------
// Also re-zeros g_agg in place so the next layer's edge scatter starts clean.
__global__ void prepack_a_kernel(const float* __restrict__ epsp) {
    int idx = blockIdx.x * blockDim.x + threadIdx.x;  // row * 80 + g4
    if (idx >= NNODES * 80) return;
    int row = idx / 80, g4 = idx % 80;
    __half2 z0[2], z1[2];
    if (g4 < 75) {
        float epv = 1.0f + __ldg(epsp);
        float4 hv = *reinterpret_cast<const float4*>(g_h + (size_t)row * HDIM + g4 * 4);
        float4 gv = *reinterpret_cast<const float4*>(g_agg + (size_t)row * HDIM + g4 * 4);
        float v[4] = {fmaf(epv, hv.x, gv.x), fmaf(epv, hv.y, gv.y),
                      fmaf(epv, hv.z, gv.z), fmaf(epv, hv.w, gv.w)};
        __half h0[4], h1[4];
#pragma unroll
        for (int j = 0; j < 4; j++) split2(v[j], h0[j], h1[j]);
        z0[0] = __halves2half2(h0[0], h0[1]);
        z0[1] = __halves2half2(h0[2], h0[3]);
        z1[0] = __halves2half2(h1[0], h1[1]);
        z1[1] = __halves2half2(h1[2], h1[3]);
        // re-zero agg for next layer
        *reinterpret_cast<float4*>(g_agg + (size_t)row * HDIM + g4 * 4) =
            make_float4(0.f, 0.f, 0.f, 0.f);
    } else {
        z0[0] = z0[1] = z1[0] = z1[1] = __halves2half2(__ushort_as_half(0), __ushort_as_half(0));
    }
    *reinterpret_cast<__half2*>(g_a0 + (size_t)row * KP1 + g4 * 4) = z0[0];
    *reinterpret_cast<__half2*>(g_a0 + (size_t)row * KP1 + g4 * 4 + 2) = z0[1];
    *reinterpret_cast<__half2*>(g_a1 + (size_t)row * KP1 + g4 * 4) = z1[0];
    *reinterpret_cast<__half2*>(g_a1 + (size_t)row * KP1 + g4 * 4 + 2) = z1[1];
}

// ---------------- Atom encoder ----------------
__global__ void atom_kernel(const int* __restrict__ x, const float* __restrict__ atom_emb) {
    int n = blockIdx.x;
    __shared__ int sx[9];
    if (threadIdx.x < 9) sx[threadIdx.x] = x[n * 9 + threadIdx.x];
    __syncthreads();
    for (int j = threadIdx.x; j < HDIM; j += blockDim.x) {
        float s = 0.f;
#pragma unroll
        for (int f = 0; f < 9; f++)
            s += __ldg(&atom_emb[((size_t)(f * 120 + sx[f])) * HDIM + j]);
        g_h[(size_t)n * HDIM + j] = s;
    }
}

// ---------------- Edge kernel: agg[dst] += relu(h[src] + e) ----------------
__global__ void edge_kernel(const int* __restrict__ edge_index,
                            const int* __restrict__ edge_attr,
                            const float* __restrict__ bond_l) {
    int e = blockIdx.x * 8 + (threadIdx.x >> 5);
    if (e >= NEDGES) return;
    int lane = threadIdx.x & 31;
    int src = __ldg(&edge_index[e]);
    int dst = __ldg(&edge_index[NEDGES + e]);
    int a0 = __ldg(&edge_attr[e * 3 + 0]);
    int a1 = __ldg(&edge_attr[e * 3 + 1]);
    int a2 = __ldg(&edge_attr[e * 3 + 2]);
    const float4* b0 = reinterpret_cast<const float4*>(bond_l + (size_t)(0 * 16 + a0) * HDIM);
    const float4* b1 = reinterpret_cast<const float4*>(bond_l + (size_t)(1 * 16 + a1) * HDIM);
    const float4* b2 = reinterpret_cast<const float4*>(bond_l + (size_t)(2 * 16 + a2) * HDIM);
    const float4* hs = reinterpret_cast<const float4*>(g_h + (size_t)src * HDIM);
    float* ag = g_agg + (size_t)dst * HDIM;
#pragma unroll 3
    for (int c = lane; c < HDIM / 4; c += 32) {
        float4 e0 = __ldg(&b0[c]);
        float4 e1 = __ldg(&b1[c]);
        float4 e2 = __ldg(&b2[c]);
        float4 hv = hs[c];
        float4 m;
        m.x = fmaxf(hv.x + e0.x + e1.x + e2.x, 0.f);
        m.y = fmaxf(hv.y + e0.y + e1.y + e2.y, 0.f);
        m.z = fmaxf(hv.z + e0.z + e1.z + e2.z, 0.f);
        m.w = fmaxf(hv.w + e0.w + e1.w + e2.w, 0.f);
        red_add_v4(ag + 4 * c, m);
    }
}

// ---------------- Tensor-core GEMM (prepacked 3xFP16 split, cp.async pipeline) ----------------
// EXACT R14 inner-loop structure (fully unrolled, unconditionally initialized
// fragments). Only addition: gemm1's all-pad half-chunk (k=304..319) is skipped
// via a uniform branch around a fully-unrolled chunk body (kc only feeds
// addressing, never array indices).
#define TILE_B 8192
#define STAGE_B (4 * TILE_B)
#define NSTAGE 3
#define GSMEM (NSTAGE * STAGE_B)

template <int MODE>
__global__ __launch_bounds__(512) void gemm_f16_kernel(
    int l,
    const float* __restrict__ bias,
    const float* __restrict__ gml, const float* __restrict__ btl,
    const float* __restrict__ mnl, const float* __restrict__ vrl) {
    constexpr int KP = (MODE == 1) ? KP1 : KP2;
    constexpr int NC = (MODE == 1) ? H2DIM : HDIM;
    constexpr int NKT = KP / 32;

    extern __shared__ __align__(128) char smem[];
    const uint32_t sb = smem_u32(smem);

    const __half* Ah = (MODE == 1) ? g_a0 : g_t0;
    const __half* Al = (MODE == 1) ? g_a1 : g_t1;
    const __half* Bh = (MODE == 1) ? (g_w1p0 + (size_t)l * H2DIM * KP1)
                                   : (g_w2p0 + (size_t)l * HDIM * KP2);
    const __half* Bl = (MODE == 1) ? (g_w1p1 + (size_t)l * H2DIM * KP1)
                                   : (g_w2p1 + (size_t)l * HDIM * KP2);

    int tid = threadIdx.x;
    int lane = tid & 31, w = tid >> 5;
    int wr = w & 3, wc = w >> 2;
    int gid = lane >> 2, tig = lane & 3;
    int ml = lane & 15, khalf = lane >> 4;
    int rowBase = blockIdx.y * 128, colBase = blockIdx.x * 128;

    // cp.async mapping: thread -> (lrow, w4); each kt advances 64 bytes along K
    int lrow = tid >> 2, w4 = tid & 3;
    int garow = rowBase + lrow;
    int gbrow = colBase + lrow;
    bool aok = (garow < NNODES);
    bool bok = (gbrow < NC);
    int sa_row = aok ? garow : 0;  // safe address base even when predicated off
    int sb_row = bok ? gbrow : 0;
    const char* pAh = reinterpret_cast<const char*>(Ah + (size_t)sa_row * KP + w4 * 8);
    const char* pAl = reinterpret_cast<const char*>(Al + (size_t)sa_row * KP + w4 * 8);
    const char* pBh = reinterpret_cast<const char*>(Bh + (size_t)sb_row * KP + w4 * 8);
    const char* pBl = reinterpret_cast<const char*>(Bl + (size_t)sb_row * KP + w4 * 8);
    uint32_t sts_off = (uint32_t)lrow * 64 + (uint32_t)((w4 ^ ((lrow >> 1) & 3)) * 16);

    float acc[2][4][4];
#pragma unroll
    for (int mt = 0; mt < 2; mt++)
#pragma unroll
        for (int nt = 0; nt < 4; nt++)
#pragma unroll
            for (int i = 0; i < 4; i++) acc[mt][nt][i] = 0.f;

    auto issue_stage = [&](int kt) {
        uint32_t st = sb + (uint32_t)(kt % NSTAGE) * STAGE_B + sts_off;
        size_t go = (size_t)kt * 64;
        cp_async16(st + 0 * TILE_B, pAh + go, aok);
        cp_async16(st + 1 * TILE_B, pAl + go, aok);
        cp_async16(st + 2 * TILE_B, pBh + go, bok);
        cp_async16(st + 3 * TILE_B, pBl + go, bok);
    };

    // Fully-unrolled chunk body; kc is runtime but ONLY feeds addressing.
    auto do_chunk = [&](uint32_t stg, int kc) {
        unsigned ahf[2][4], alf[2][4], bhf[2][4], blf[2][4];
#pragma unroll
        for (int mt = 0; mt < 2; mt++) {
            int r = wr * 32 + mt * 16 + ml;
            uint32_t off = (uint32_t)r * 64 +
                           (uint32_t)(((kc * 2 + khalf) ^ ((r >> 1) & 3)) * 16);
            ldm_x4(ahf[mt], stg + 0 * TILE_B + off);
            ldm_x4(alf[mt], stg + 1 * TILE_B + off);
        }
#pragma unroll
        for (int ng = 0; ng < 2; ng++) {
            int r = wc * 32 + ng * 16 + ml;
            uint32_t off = (uint32_t)r * 64 +
                           (uint32_t)(((kc * 2 + khalf) ^ ((r >> 1) & 3)) * 16);
            ldm_x4(bhf[ng], stg + 2 * TILE_B + off);
            ldm_x4(blf[ng], stg + 3 * TILE_B + off);
        }
#pragma unroll
        for (int mt = 0; mt < 2; mt++)
#pragma unroll
            for (int ng = 0; ng < 2; ng++)
#pragma unroll
                for (int sn = 0; sn < 2; sn++) {
                    unsigned bh2[2] = {bhf[ng][sn], bhf[ng][sn + 2]};
                    unsigned bl2[2] = {blf[ng][sn], blf[ng][sn + 2]};
                    float* a = acc[mt][ng * 2 + sn];
                    mma_f16(a, ahf[mt], bh2);
                    mma_f16(a, ahf[mt], bl2);
                    mma_f16(a, alf[mt], bh2);
                }
    };

    issue_stage(0);
    cp_commit();
    issue_stage(1);
    cp_commit();

    for (int kt = 0; kt < NKT; kt++) {
        if (kt + 2 < NKT) issue_stage(kt + 2);
        cp_commit();
        cp_wait<2>();
        __syncthreads();

        uint32_t stg = sb + (uint32_t)(kt % NSTAGE) * STAGE_B;
        do_chunk(stg, 0);
        // gemm1: final chunk's kc=1 covers k=304..319, all zero padding -> skip
        if (MODE == 2 || kt < NKT - 1) do_chunk(stg, 1);
        __syncthreads();
    }

    // ---- Epilogue ----
#pragma unroll
    for (int mt = 0; mt < 2; mt++)
#pragma unroll
        for (int ng = 0; ng < 2; ng++)
#pragma unroll
            for (int sn = 0; sn < 2; sn++) {
                int c = colBase + wc * 32 + ng * 16 + sn * 8 + 2 * tig;
                int r0 = rowBase + wr * 32 + mt * 16 + gid;
                int r1 = r0 + 8;
                float* a = acc[mt][ng * 2 + sn];
                if (MODE == 1) {
                    if (c < H2DIM) {
                        float s0 = __ldg(&gml[c]) * rsqrtf(__ldg(&vrl[c]) + 1e-5f);
                        float t0 = (__ldg(&bias[c]) - __ldg(&mnl[c])) * s0 + __ldg(&btl[c]);
                        float s1 = __ldg(&gml[c + 1]) * rsqrtf(__ldg(&vrl[c + 1]) + 1e-5f);
                        float t1 = (__ldg(&bias[c + 1]) - __ldg(&mnl[c + 1])) * s1 + __ldg(&btl[c + 1]);
                        if (r0 < NNODES) {
                            float v0 = fmaxf(fmaf(a[0], s0, t0), 0.f);
                            float v1 = fmaxf(fmaf(a[1], s1, t1), 0.f);
                            __half h00, h01, h10, h11;
                            split2(v0, h00, h10);
                            split2(v1, h01, h11);
                            *reinterpret_cast<__half2*>(g_t0 + (size_t)r0 * KP2 + c) =
                                __halves2half2(h00, h01);
                            *reinterpret_cast<__half2*>(g_t1 + (size_t)r0 * KP2 + c) =
                                __halves2half2(h10, h11);
                        }
                        if (r1 < NNODES) {
                            float v0 = fmaxf(fmaf(a[2], s0, t0), 0.f);
                            float v1 = fmaxf(fmaf(a[3], s1, t1), 0.f);
                            __half h00, h01, h10, h11;
                            split2(v0, h00, h10);
                            split2(v1, h01, h11);
                            *reinterpret_cast<__half2*>(g_t0 + (size_t)r1 * KP2 + c) =
                                __halves2half2(h00, h01);
                            *reinterpret_cast<__half2*>(g_t1 + (size_t)r1 * KP2 + c) =
                                __halves2half2(h10, h11);
                        }
                    } else if (c < KP2) {
                        __half2 z = __halves2half2(__ushort_as_half(0), __ushort_as_half(0));
                        if (r0 < NNODES) {
                            *reinterpret_cast<__half2*>(g_t0 + (size_t)r0 * KP2 + c) = z;
                            *reinterpret_cast<__half2*>(g_t1 + (size_t)r0 * KP2 + c) = z;
                        }
                        if (r1 < NNODES) {
                            *reinterpret_cast<__half2*>(g_t0 + (size_t)r1 * KP2 + c) = z;
                            *reinterpret_cast<__half2*>(g_t1 + (size_t)r1 * KP2 + c) = z;
                        }
                    }
                } else {
                    if (c < HDIM) {
                        float t0 = __ldg(&bias[c]);
                        float t1 = __ldg(&bias[c + 1]);
                        if (r0 < NNODES) {
                            float2 o = make_float2(a[0] + t0, a[1] + t1);
                            *reinterpret_cast<float2*>(g_h + (size_t)r0 * HDIM + c) = o;
                        }
                        if (r1 < NNODES) {
                            float2 o = make_float2(a[2] + t0, a[3] + t1);
                            *reinterpret_cast<float2*>(g_h + (size_t)r1 * HDIM + c) = o;
                        }
                    }
                }
            }
}

// ---------------- Pooling scatter ----------------
__global__ void pool_kernel(const int* __restrict__ batch) {
    int n = blockIdx.x * 8 + (threadIdx.x >> 5);
    if (n >= NNODES) return;
    int lane = threadIdx.x & 31;
    int g = __ldg(&batch[n]);
    const float4* hr = reinterpret_cast<const float4*>(g_h + (size_t)n * HDIM);
    float* gs = g_gsum + (size_t)g * HDIM;
#pragma unroll 3
    for (int c = lane; c < HDIM / 4; c += 32)
        red_add_v4(gs + 4 * c, hr[c]);
    if (lane == 0) atomicAdd(&g_gcnt[g], 1.0f);
}

// ---------------- Final: graph_feature + logits ----------------
__global__ void final_kernel(const float* __restrict__ cls_W, const float* __restrict__ cls_b,
                             float* __restrict__ out, int write_gf) {
    int g = blockIdx.x;
    int tid = threadIdx.x;
    float inv = 1.0f / fmaxf(g_gcnt[g], 1.0f);
    float d0 = 0.f, d1 = 0.f;
    for (int j = tid; j < HDIM; j += blockDim.x) {
        float gf = g_gsum[(size_t)g * HDIM + j] * inv;
        if (write_gf) out[2 * NGRAPHS + (size_t)g * HDIM + j] = gf;
        d0 += gf * __ldg(&cls_W[j * 2 + 0]);
        d1 += gf * __ldg(&cls_W[j * 2 + 1]);
    }
    __shared__ float s0[128], s1[128];
    s0[tid] = d0;
    s1[tid] = d1;
    __syncthreads();
    for (int o = 64; o > 0; o >>= 1) {
        if (tid < o) { s0[tid] += s0[tid + o]; s1[tid] += s1[tid + o]; }
        __syncthreads();
    }
    if (tid == 0) {
        out[g * 2 + 0] = s0[0] + __ldg(&cls_b[0]);
        out[g * 2 + 1] = s1[0] + __ldg(&cls_b[1]);
    }
}

// ---------------- Launcher ----------------
extern "C" void kernel_launch(void* const* d_in, const int* in_sizes, int n_in,
                              void* d_out, int out_size) {
    const int* x          = (const int*)d_in[0];
    const int* edge_index = (const int*)d_in[1];
    const int* edge_attr  = (const int*)d_in[2];
    const int* batch      = (const int*)d_in[3];
    const float* atom_emb = (const float*)d_in[4];
    const float* bond_emb = (const float*)d_in[5];
    const float* eps      = (const float*)d_in[6];
    const float* W1       = (const float*)d_in[7];
    const float* b1       = (const float*)d_in[8];
    const float* bn_gamma = (const float*)d_in[9];
    const float* bn_beta  = (const float*)d_in[10];
    const float* bn_mean  = (const float*)d_in[11];
    const float* bn_var   = (const float*)d_in[12];
    const float* W2       = (const float*)d_in[13];
    const float* b2       = (const float*)d_in[14];
    const float* cls_W    = (const float*)d_in[15];
    const float* cls_b    = (const float*)d_in[16];
    float* out = (float*)d_out;

    cudaFuncSetAttribute(gemm_f16_kernel<1>, cudaFuncAttributeMaxDynamicSharedMemorySize, GSMEM);
    cudaFuncSetAttribute(gemm_f16_kernel<2>, cudaFuncAttributeMaxDynamicSharedMemorySize, GSMEM);

    atom_kernel<<<NNODES, 128>>>(x, atom_emb);
    zero_pool_kernel<<<1184, 256>>>();
    prepack_w_kernel<<<(W1P_TOTAL + W2P_TOTAL + 255) / 256, 256>>>(W1, W2);
    zero_agg_kernel<<<4096, 256>>>();  // layer 0 only; prepack_a re-zeros thereafter

    dim3 g1grid(5, (NNODES + 127) / 128);
    dim3 g2grid(3, (NNODES + 127) / 128);

    for (int l = 0; l < NLAYERS; l++) {
        edge_kernel<<<(NEDGES + 7) / 8, 256>>>(edge_index, edge_attr,
                                               bond_emb + (size_t)l * 3 * 16 * HDIM);
        prepack_a_kernel<<<(NNODES * 80 + 255) / 256, 256>>>(eps + l);
        gemm_f16_kernel<1><<<g1grid, 512, GSMEM>>>(
            l, b1 + (size_t)l * H2DIM,
            bn_gamma + (size_t)l * H2DIM, bn_beta + (size_t)l * H2DIM,
            bn_mean + (size_t)l * H2DIM, bn_var + (size_t)l * H2DIM);
        gemm_f16_kernel<2><<<g2grid, 512, GSMEM>>>(
            l, b2 + (size_t)l * HDIM, nullptr, nullptr, nullptr, nullptr);
    }

    pool_kernel<<<(NNODES + 7) / 8, 256>>>(batch);
    int write_gf = (out_size >= 2 * NGRAPHS + NGRAPHS * HDIM) ? 1 : 0;
    final_kernel<<<NGRAPHS, 128>>>(cls_W, cls_b, out, write_gf);
}